// round 10
// baseline (speedup 1.0000x reference)
#include <cuda_runtime.h>
#include <cstdint>

// ---------------- problem constants ----------------
#define NS      524288
#define NEXP    16
#define HID     256
#define OUTD    3

// ---------------- tiling ----------------
#define TPB     128                 // threads per block (mlp)
#define SPT     8                   // samples per thread (mlp)
#define SPB     (TPB * SPT)         // 1024 samples per mlp tile
#define MAXBLK  ((NS / SPB) + NEXP) // 528 tiles upper bound
#define SBLK    512                 // scatter blocks
#define SSPT    4                   // 512 * 256 * 4 = 524288
#define CAP     NS                  // per-expert region capacity
#define CSTRIDE 32                  // cursor padding (128B apart)

typedef unsigned long long u64;

// ---------------- device scratch (static; zero-init is the "reset" state) ----------------
__device__ int g_sidx[NEXP * CAP];        // expert-partitioned original indices
__device__ int g_cur[NEXP * CSTRIDE];     // RELATIVE cursors (start at 0)
__device__ int g_done;                    // scatter completion ticket
__device__ int g_fin;                     // mlp completion ticket
__device__ int g_cnt[NEXP];               // per-expert counts
__device__ int g_bmap[MAXBLK];            // tile -> (expert<<16 | tile_in_expert), -1 idle

// ---------------- helpers ----------------
__device__ __forceinline__ int expert_of(float x0, float x1) {
    int i = (int)floorf(x0 * 4.0f);
    int j = (int)floorf(x1 * 4.0f);
    i = max(0, min(3, i));
    j = max(0, min(3, j));
    return j * 4 + i;
}
__device__ __forceinline__ u64 f2fma(u64 a, u64 b, u64 c) {
    u64 d;
    asm("fma.rn.f32x2 %0, %1, %2, %3;" : "=l"(d) : "l"(a), "l"(b), "l"(c));
    return d;
}
__device__ __forceinline__ u64 f2pack(float lo, float hi) {
    u64 d;
    asm("mov.b64 %0, {%1, %2};" : "=l"(d) : "f"(lo), "f"(hi));
    return d;
}
__device__ __forceinline__ float2 f2unpack(u64 v) {
    float2 r;
    asm("mov.b64 {%0, %1}, %2;" : "=f"(r.x), "=f"(r.y) : "l"(v));
    return r;
}
__device__ __forceinline__ u64 f2relu(u64 v) {
    float2 r = f2unpack(v);
    return f2pack(fmaxf(r.x, 0.0f), fmaxf(r.y, 0.0f));
}

// ---------------- K1: single-pass expert scatter (index-only) + tile map ----------------
__global__ void __launch_bounds__(256) k_scatter(const float2* __restrict__ s) {
    __shared__ int sc[NEXP], sb[NEXP], sr[NEXP];
    int tid  = threadIdx.x;
    int lane = tid & 31;
    unsigned lt_mask = (1u << lane) - 1u;

    if (tid < NEXP) { sc[tid] = 0; sr[tid] = 0; }
    __syncthreads();

    int base = blockIdx.x * (256 * SSPT);
    int e[SSPT];

    // Phase 1: block histogram (warp-aggregated)
    #pragma unroll
    for (int t = 0; t < SSPT; t++) {
        float2 xy = s[base + t * 256 + tid];
        e[t] = expert_of(xy.x, xy.y);
        unsigned m = __match_any_sync(0xffffffffu, e[t]);
        if ((__ffs(m) - 1) == lane) atomicAdd(&sc[e[t]], __popc(m));
    }
    __syncthreads();

    if (tid < NEXP) sb[tid] = atomicAdd(&g_cur[tid * CSTRIDE], sc[tid]);
    __syncthreads();

    // Phase 2: ranked scatter (warp-aggregated) — indices only
    #pragma unroll
    for (int t = 0; t < SSPT; t++) {
        unsigned m = __match_any_sync(0xffffffffu, e[t]);
        int leader = __ffs(m) - 1;
        int rank   = __popc(m & lt_mask);
        int wbase  = 0;
        if (lane == leader) wbase = atomicAdd(&sr[e[t]], __popc(m));
        wbase = __shfl_sync(0xffffffffu, wbase, leader);
        g_sidx[e[t] * CAP + sb[e[t]] + wbase + rank] = base + t * 256 + tid;
    }

    // Last block builds tile map
    __threadfence();
    __syncthreads();
    __shared__ int is_last;
    if (tid == 0) is_last = (atomicAdd(&g_done, 1) == gridDim.x - 1) ? 1 : 0;
    __syncthreads();
    if (!is_last) return;

    __shared__ int cnt[NEXP], toff[NEXP + 1];
    if (tid < NEXP) cnt[tid] = g_cur[tid * CSTRIDE];
    __syncthreads();
    if (tid == 0) {
        int o = 0;
        for (int ee = 0; ee < NEXP; ee++) {
            toff[ee] = o;
            o += (cnt[ee] + SPB - 1) / SPB;
        }
        toff[NEXP] = o;
    }
    __syncthreads();
    for (int b = tid; b < MAXBLK; b += 256) g_bmap[b] = -1;
    if (tid < NEXP) g_cnt[tid] = cnt[tid];
    __syncthreads();
    if (tid < NEXP) {
        int ntile = toff[tid + 1] - toff[tid];
        for (int t = 0; t < ntile; t++)
            g_bmap[toff[tid] + t] = (tid << 16) | t;
    }
}

// ---------------- K2: expert-uniform fused MLP (8 chains/thread, packed weights) ----------------
__global__ void __launch_bounds__(TPB, 4) k_mlp(const float2* __restrict__ s,
                                                const float* __restrict__ W1,
                                                const float* __restrict__ b1,
                                                const float* __restrict__ W2,
                                                const float* __restrict__ b2,
                                                float* __restrict__ out) {
    int v = g_bmap[blockIdx.x];
    // packed weights: per hidden pair p (12 floats = 3 x ulonglong2):
    // [w0lo w0hi | w1lo w1hi | bblo bbhi | v0lo v0hi | v1lo v1hi | v2lo v2hi]
    __shared__ float sw[128 * 12];

    if (v >= 0) {
        int e    = v >> 16;
        int tile = v & 0xffff;

        {
            int p = threadIdx.x;   // TPB == 128 == number of hidden pairs
            int h = 2 * p;
            sw[p * 12 + 0]  = W1[e * 512 + h];
            sw[p * 12 + 1]  = W1[e * 512 + h + 1];
            sw[p * 12 + 2]  = W1[e * 512 + 256 + h];
            sw[p * 12 + 3]  = W1[e * 512 + 256 + h + 1];
            sw[p * 12 + 4]  = b1[e * 256 + h];
            sw[p * 12 + 5]  = b1[e * 256 + h + 1];
            sw[p * 12 + 6]  = W2[(e * 256 + h) * 3 + 0];
            sw[p * 12 + 7]  = W2[(e * 256 + h + 1) * 3 + 0];
            sw[p * 12 + 8]  = W2[(e * 256 + h) * 3 + 1];
            sw[p * 12 + 9]  = W2[(e * 256 + h + 1) * 3 + 1];
            sw[p * 12 + 10] = W2[(e * 256 + h) * 3 + 2];
            sw[p * 12 + 11] = W2[(e * 256 + h + 1) * 3 + 2];
        }
        int rbase = e * CAP + tile * SPB;
        int rend  = e * CAP + g_cnt[e];
        __syncthreads();

        u64 xx0[SPT], xx1[SPT];
        #pragma unroll
        for (int t = 0; t < SPT; t++) {
            int slot = rbase + t * TPB + threadIdx.x;
            int idx  = (slot < rend) ? g_sidx[slot] : 0;
            float2 xy = __ldg(&s[idx]);
            xx0[t] = f2pack(xy.x, xy.x);
            xx1[t] = f2pack(xy.y, xy.y);
        }

        u64 acc0[SPT], acc1[SPT], acc2[SPT];
        #pragma unroll
        for (int t = 0; t < SPT; t++) { acc0[t] = 0ull; acc1[t] = 0ull; acc2[t] = 0ull; }

        const ulonglong2* swq = (const ulonglong2*)sw;
        #pragma unroll 8
        for (int p = 0; p < 128; p++) {
            ulonglong2 q0 = swq[p * 3 + 0];   // w0, w1
            ulonglong2 q1 = swq[p * 3 + 1];   // bb, v0
            ulonglong2 q2 = swq[p * 3 + 2];   // v1, v2
            #pragma unroll
            for (int t = 0; t < SPT; t++) {
                u64 h = f2fma(xx0[t], q0.x, f2fma(xx1[t], q0.y, q1.x));
                h = f2relu(h);
                acc0[t] = f2fma(h, q1.y, acc0[t]);
                acc1[t] = f2fma(h, q2.x, acc1[t]);
                acc2[t] = f2fma(h, q2.y, acc2[t]);
            }
        }

        float c0 = __ldg(&b2[e * 3 + 0]);
        float c1 = __ldg(&b2[e * 3 + 1]);
        float c2 = __ldg(&b2[e * 3 + 2]);
        #pragma unroll
        for (int t = 0; t < SPT; t++) {
            int slot = rbase + t * TPB + threadIdx.x;
            if (slot >= rend) continue;
            int idx = g_sidx[slot];           // L1 hit (read in prologue)
            float2 a0 = f2unpack(acc0[t]);
            float2 a1 = f2unpack(acc1[t]);
            float2 a2 = f2unpack(acc2[t]);
            float* o = out + (size_t)idx * 3;
            o[0] = a0.x + a0.y + c0;
            o[1] = a1.x + a1.y + c1;
            o[2] = a2.x + a2.y + c2;
        }
    }

    // per-replay state reset: last block to finish clears cursors/tickets
    if (threadIdx.x == 0) {
        __threadfence();
        if (atomicAdd(&g_fin, 1) == (int)gridDim.x - 1) {
            g_fin  = 0;
            g_done = 0;
            #pragma unroll
            for (int ee = 0; ee < NEXP; ee++) g_cur[ee * CSTRIDE] = 0;
        }
    }
}

// ---------------- launch ----------------
extern "C" void kernel_launch(void* const* d_in, const int* in_sizes, int n_in,
                              void* d_out, int out_size) {
    const float* samples = (const float*)d_in[0];
    const float* W1      = (const float*)d_in[1];
    const float* b1      = (const float*)d_in[2];
    const float* W2      = (const float*)d_in[3];
    const float* b2      = (const float*)d_in[4];
    float* out           = (float*)d_out;

    k_scatter<<<SBLK, 256>>>((const float2*)samples);
    k_mlp<<<MAXBLK, TPB>>>((const float2*)samples, W1, b1, W2, b2, out);
}

// round 13
// speedup vs baseline: 1.0045x; 1.0045x over previous
#include <cuda_runtime.h>
#include <cstdint>

// ---------------- problem constants ----------------
#define NS      524288
#define NEXP    16
#define HID     256
#define OUTD    3

// ---------------- tiling ----------------
#define TPB     128                 // threads per block (mlp)
#define SPT     8                   // samples per thread (mlp)
#define SPB     (TPB * SPT)         // 1024 samples per mlp tile
#define MAXBLK  ((NS / SPB) + NEXP) // 528 tiles upper bound
#define SBLK    512                 // scatter blocks
#define SSPT    4                   // 512 * 256 * 4 = 524288
#define CAP     NS                  // per-expert region capacity
#define CSTRIDE 32                  // cursor padding (128B apart)

typedef unsigned long long u64;

// ---------------- device scratch (static; zero-init is the "reset" state) ----------------
__device__ int g_sidx[NEXP * CAP];        // expert-partitioned original indices
__device__ int g_cur[NEXP * CSTRIDE];     // RELATIVE cursors (start at 0)
__device__ int g_done;                    // scatter completion ticket
__device__ int g_fin;                     // mlp completion ticket
__device__ int g_cnt[NEXP];               // per-expert counts
__device__ int g_bmap[MAXBLK];            // tile -> (expert<<16 | tile_in_expert), -1 idle

// ---------------- helpers ----------------
__device__ __forceinline__ int expert_of(float x0, float x1) {
    int i = (int)floorf(x0 * 4.0f);
    int j = (int)floorf(x1 * 4.0f);
    i = max(0, min(3, i));
    j = max(0, min(3, j));
    return j * 4 + i;
}
__device__ __forceinline__ u64 f2fma(u64 a, u64 b, u64 c) {
    u64 d;
    asm("fma.rn.f32x2 %0, %1, %2, %3;" : "=l"(d) : "l"(a), "l"(b), "l"(c));
    return d;
}
__device__ __forceinline__ u64 f2pack(float lo, float hi) {
    u64 d;
    asm("mov.b64 %0, {%1, %2};" : "=l"(d) : "f"(lo), "f"(hi));
    return d;
}
__device__ __forceinline__ float2 f2unpack(u64 v) {
    float2 r;
    asm("mov.b64 {%0, %1}, %2;" : "=f"(r.x), "=f"(r.y) : "l"(v));
    return r;
}
__device__ __forceinline__ u64 f2relu(u64 v) {
    float2 r = f2unpack(v);
    return f2pack(fmaxf(r.x, 0.0f), fmaxf(r.y, 0.0f));
}

// ---------------- K1: single-pass expert scatter (index-only) + tile map ----------------
__global__ void __launch_bounds__(256) k_scatter(const float2* __restrict__ s) {
    __shared__ int sc[NEXP], sb[NEXP], sr[NEXP];
    int tid  = threadIdx.x;
    int lane = tid & 31;
    unsigned lt_mask = (1u << lane) - 1u;

    if (tid < NEXP) { sc[tid] = 0; sr[tid] = 0; }
    __syncthreads();

    int base = blockIdx.x * (256 * SSPT);
    int e[SSPT];

    // Phase 1: block histogram (warp-aggregated)
    #pragma unroll
    for (int t = 0; t < SSPT; t++) {
        float2 xy = s[base + t * 256 + tid];
        e[t] = expert_of(xy.x, xy.y);
        unsigned m = __match_any_sync(0xffffffffu, e[t]);
        if ((__ffs(m) - 1) == lane) atomicAdd(&sc[e[t]], __popc(m));
    }
    __syncthreads();

    if (tid < NEXP) sb[tid] = atomicAdd(&g_cur[tid * CSTRIDE], sc[tid]);
    __syncthreads();

    // Phase 2: ranked scatter (warp-aggregated) — indices only
    #pragma unroll
    for (int t = 0; t < SSPT; t++) {
        unsigned m = __match_any_sync(0xffffffffu, e[t]);
        int leader = __ffs(m) - 1;
        int rank   = __popc(m & lt_mask);
        int wbase  = 0;
        if (lane == leader) wbase = atomicAdd(&sr[e[t]], __popc(m));
        wbase = __shfl_sync(0xffffffffu, wbase, leader);
        g_sidx[e[t] * CAP + sb[e[t]] + wbase + rank] = base + t * 256 + tid;
    }

    // Last block builds tile map
    __threadfence();
    __syncthreads();
    __shared__ int is_last;
    if (tid == 0) is_last = (atomicAdd(&g_done, 1) == gridDim.x - 1) ? 1 : 0;
    __syncthreads();
    if (!is_last) return;

    __shared__ int cnt[NEXP], toff[NEXP + 1];
    if (tid < NEXP) cnt[tid] = g_cur[tid * CSTRIDE];
    __syncthreads();
    if (tid == 0) {
        int o = 0;
        for (int ee = 0; ee < NEXP; ee++) {
            toff[ee] = o;
            o += (cnt[ee] + SPB - 1) / SPB;
        }
        toff[NEXP] = o;
    }
    __syncthreads();
    for (int b = tid; b < MAXBLK; b += 256) g_bmap[b] = -1;
    if (tid < NEXP) g_cnt[tid] = cnt[tid];
    __syncthreads();
    if (tid < NEXP) {
        int ntile = toff[tid + 1] - toff[tid];
        for (int t = 0; t < ntile; t++)
            g_bmap[toff[tid] + t] = (tid << 16) | t;
    }
}

// ---------------- K2: expert-uniform fused MLP (8 chains/thread, packed weights) ----------------
__global__ void __launch_bounds__(TPB, 4) k_mlp(const float2* __restrict__ s,
                                                const float* __restrict__ W1,
                                                const float* __restrict__ b1,
                                                const float* __restrict__ W2,
                                                const float* __restrict__ b2,
                                                float* __restrict__ out) {
    int v = g_bmap[blockIdx.x];
    // packed weights: per hidden pair p (12 floats = 3 x ulonglong2):
    // [w0lo w0hi | w1lo w1hi | bblo bbhi | v0lo v0hi | v1lo v1hi | v2lo v2hi]
    __shared__ float sw[128 * 12];

    if (v >= 0) {
        int e    = v >> 16;
        int tile = v & 0xffff;

        {
            int p = threadIdx.x;   // TPB == 128 == number of hidden pairs
            int h = 2 * p;
            sw[p * 12 + 0]  = W1[e * 512 + h];
            sw[p * 12 + 1]  = W1[e * 512 + h + 1];
            sw[p * 12 + 2]  = W1[e * 512 + 256 + h];
            sw[p * 12 + 3]  = W1[e * 512 + 256 + h + 1];
            sw[p * 12 + 4]  = b1[e * 256 + h];
            sw[p * 12 + 5]  = b1[e * 256 + h + 1];
            sw[p * 12 + 6]  = W2[(e * 256 + h) * 3 + 0];
            sw[p * 12 + 7]  = W2[(e * 256 + h + 1) * 3 + 0];
            sw[p * 12 + 8]  = W2[(e * 256 + h) * 3 + 1];
            sw[p * 12 + 9]  = W2[(e * 256 + h + 1) * 3 + 1];
            sw[p * 12 + 10] = W2[(e * 256 + h) * 3 + 2];
            sw[p * 12 + 11] = W2[(e * 256 + h + 1) * 3 + 2];
        }
        int rbase = e * CAP + tile * SPB;
        int rend  = e * CAP + g_cnt[e];
        __syncthreads();

        u64 xx0[SPT], xx1[SPT];
        #pragma unroll
        for (int t = 0; t < SPT; t++) {
            int slot = rbase + t * TPB + threadIdx.x;
            int idx  = (slot < rend) ? g_sidx[slot] : 0;
            float2 xy = __ldg(&s[idx]);
            xx0[t] = f2pack(xy.x, xy.x);
            xx1[t] = f2pack(xy.y, xy.y);
        }

        u64 acc0[SPT], acc1[SPT], acc2[SPT];
        #pragma unroll
        for (int t = 0; t < SPT; t++) { acc0[t] = 0ull; acc1[t] = 0ull; acc2[t] = 0ull; }

        const ulonglong2* swq = (const ulonglong2*)sw;
        #pragma unroll 8
        for (int p = 0; p < 128; p++) {
            ulonglong2 q0 = swq[p * 3 + 0];   // w0, w1
            ulonglong2 q1 = swq[p * 3 + 1];   // bb, v0
            ulonglong2 q2 = swq[p * 3 + 2];   // v1, v2
            #pragma unroll
            for (int t = 0; t < SPT; t++) {
                u64 h = f2fma(xx0[t], q0.x, f2fma(xx1[t], q0.y, q1.x));
                h = f2relu(h);
                acc0[t] = f2fma(h, q1.y, acc0[t]);
                acc1[t] = f2fma(h, q2.x, acc1[t]);
                acc2[t] = f2fma(h, q2.y, acc2[t]);
            }
        }

        float c0 = __ldg(&b2[e * 3 + 0]);
        float c1 = __ldg(&b2[e * 3 + 1]);
        float c2 = __ldg(&b2[e * 3 + 2]);
        #pragma unroll
        for (int t = 0; t < SPT; t++) {
            int slot = rbase + t * TPB + threadIdx.x;
            if (slot >= rend) continue;
            int idx = g_sidx[slot];           // L1 hit (read in prologue)
            float2 a0 = f2unpack(acc0[t]);
            float2 a1 = f2unpack(acc1[t]);
            float2 a2 = f2unpack(acc2[t]);
            float* o = out + (size_t)idx * 3;
            o[0] = a0.x + a0.y + c0;
            o[1] = a1.x + a1.y + c1;
            o[2] = a2.x + a2.y + c2;
        }
    }

    // per-replay state reset: last block to finish clears cursors/tickets
    if (threadIdx.x == 0) {
        __threadfence();
        if (atomicAdd(&g_fin, 1) == (int)gridDim.x - 1) {
            g_fin  = 0;
            g_done = 0;
            #pragma unroll
            for (int ee = 0; ee < NEXP; ee++) g_cur[ee * CSTRIDE] = 0;
        }
    }
}

// ---------------- launch ----------------
extern "C" void kernel_launch(void* const* d_in, const int* in_sizes, int n_in,
                              void* d_out, int out_size) {
    const float* samples = (const float*)d_in[0];
    const float* W1      = (const float*)d_in[1];
    const float* b1      = (const float*)d_in[2];
    const float* W2      = (const float*)d_in[3];
    const float* b2      = (const float*)d_in[4];
    float* out           = (float*)d_out;

    k_scatter<<<SBLK, 256>>>((const float2*)samples);
    k_mlp<<<MAXBLK, TPB>>>((const float2*)samples, W1, b1, W2, b2, out);
}

// round 15
// speedup vs baseline: 1.0078x; 1.0032x over previous
#include <cuda_runtime.h>
#include <cstdint>

// ---------------- problem constants ----------------
#define NS      524288
#define NEXP    16
#define HID     256
#define OUTD    3

// ---------------- tiling ----------------
#define TPB     128                 // threads per block (mlp)
#define SPT     8                   // samples per thread (mlp)
#define SPB     (TPB * SPT)         // 1024 samples per mlp tile
#define MAXBLK  ((NS / SPB) + NEXP) // 528 tiles upper bound
#define SBLK    512                 // scatter blocks
#define SSPT    4                   // 512 * 256 * 4 = 524288
#define CAP     NS                  // per-expert region capacity
#define CSTRIDE 32                  // cursor padding (128B apart)

typedef unsigned long long u64;

// ---------------- device scratch (static; zero-init is the "reset" state) ----------------
__device__ int g_sidx[NEXP * CAP];        // expert-partitioned original indices
__device__ int g_cur[NEXP * CSTRIDE];     // RELATIVE cursors (start at 0)
__device__ int g_done;                    // scatter completion ticket
__device__ int g_fin;                     // mlp completion ticket
__device__ int g_cnt[NEXP];               // per-expert counts
__device__ int g_bmap[MAXBLK];            // tile -> (expert<<16 | tile_in_expert), -1 idle

// ---------------- helpers ----------------
__device__ __forceinline__ int expert_of(float x0, float x1) {
    int i = (int)floorf(x0 * 4.0f);
    int j = (int)floorf(x1 * 4.0f);
    i = max(0, min(3, i));
    j = max(0, min(3, j));
    return j * 4 + i;
}
__device__ __forceinline__ u64 f2fma(u64 a, u64 b, u64 c) {
    u64 d;
    asm("fma.rn.f32x2 %0, %1, %2, %3;" : "=l"(d) : "l"(a), "l"(b), "l"(c));
    return d;
}
__device__ __forceinline__ u64 f2pack(float lo, float hi) {
    u64 d;
    asm("mov.b64 %0, {%1, %2};" : "=l"(d) : "f"(lo), "f"(hi));
    return d;
}
__device__ __forceinline__ float2 f2unpack(u64 v) {
    float2 r;
    asm("mov.b64 {%0, %1}, %2;" : "=f"(r.x), "=f"(r.y) : "l"(v));
    return r;
}
__device__ __forceinline__ u64 f2relu(u64 v) {
    float2 r = f2unpack(v);
    return f2pack(fmaxf(r.x, 0.0f), fmaxf(r.y, 0.0f));
}

// ---------------- K1: single-pass expert scatter (index-only) + tile map ----------------
__global__ void __launch_bounds__(256) k_scatter(const float2* __restrict__ s) {
    __shared__ int sc[NEXP], sb[NEXP], sr[NEXP];
    int tid  = threadIdx.x;
    int lane = tid & 31;
    unsigned lt_mask = (1u << lane) - 1u;

    if (tid < NEXP) { sc[tid] = 0; sr[tid] = 0; }
    __syncthreads();

    int base = blockIdx.x * (256 * SSPT);
    int e[SSPT];

    // Phase 1: block histogram (warp-aggregated)
    #pragma unroll
    for (int t = 0; t < SSPT; t++) {
        float2 xy = s[base + t * 256 + tid];
        e[t] = expert_of(xy.x, xy.y);
        unsigned m = __match_any_sync(0xffffffffu, e[t]);
        if ((__ffs(m) - 1) == lane) atomicAdd(&sc[e[t]], __popc(m));
    }
    __syncthreads();

    if (tid < NEXP) sb[tid] = atomicAdd(&g_cur[tid * CSTRIDE], sc[tid]);
    __syncthreads();

    // Phase 2: ranked scatter (warp-aggregated) — indices only
    #pragma unroll
    for (int t = 0; t < SSPT; t++) {
        unsigned m = __match_any_sync(0xffffffffu, e[t]);
        int leader = __ffs(m) - 1;
        int rank   = __popc(m & lt_mask);
        int wbase  = 0;
        if (lane == leader) wbase = atomicAdd(&sr[e[t]], __popc(m));
        wbase = __shfl_sync(0xffffffffu, wbase, leader);
        g_sidx[e[t] * CAP + sb[e[t]] + wbase + rank] = base + t * 256 + tid;
    }

    // Last block builds tile map
    __threadfence();
    __syncthreads();
    __shared__ int is_last;
    if (tid == 0) is_last = (atomicAdd(&g_done, 1) == gridDim.x - 1) ? 1 : 0;
    __syncthreads();
    if (!is_last) return;

    __shared__ int cnt[NEXP], toff[NEXP + 1];
    if (tid < NEXP) cnt[tid] = g_cur[tid * CSTRIDE];
    __syncthreads();
    if (tid == 0) {
        int o = 0;
        for (int ee = 0; ee < NEXP; ee++) {
            toff[ee] = o;
            o += (cnt[ee] + SPB - 1) / SPB;
        }
        toff[NEXP] = o;
    }
    __syncthreads();
    for (int b = tid; b < MAXBLK; b += 256) g_bmap[b] = -1;
    if (tid < NEXP) g_cnt[tid] = cnt[tid];
    __syncthreads();
    if (tid < NEXP) {
        int ntile = toff[tid + 1] - toff[tid];
        for (int t = 0; t < ntile; t++)
            g_bmap[toff[tid] + t] = (tid << 16) | t;
    }
}

// ---------------- K2: expert-uniform fused MLP (8 chains/thread, packed weights) ----------------
__global__ void __launch_bounds__(TPB, 4) k_mlp(const float2* __restrict__ s,
                                                const float* __restrict__ W1,
                                                const float* __restrict__ b1,
                                                const float* __restrict__ W2,
                                                const float* __restrict__ b2,
                                                float* __restrict__ out) {
    int v = g_bmap[blockIdx.x];
    // packed weights: per hidden pair p (12 floats = 3 x ulonglong2):
    // [w0lo w0hi | w1lo w1hi | bblo bbhi | v0lo v0hi | v1lo v1hi | v2lo v2hi]
    __shared__ float sw[128 * 12];

    if (v >= 0) {
        int e    = v >> 16;
        int tile = v & 0xffff;

        {
            int p = threadIdx.x;   // TPB == 128 == number of hidden pairs
            int h = 2 * p;
            sw[p * 12 + 0]  = W1[e * 512 + h];
            sw[p * 12 + 1]  = W1[e * 512 + h + 1];
            sw[p * 12 + 2]  = W1[e * 512 + 256 + h];
            sw[p * 12 + 3]  = W1[e * 512 + 256 + h + 1];
            sw[p * 12 + 4]  = b1[e * 256 + h];
            sw[p * 12 + 5]  = b1[e * 256 + h + 1];
            sw[p * 12 + 6]  = W2[(e * 256 + h) * 3 + 0];
            sw[p * 12 + 7]  = W2[(e * 256 + h + 1) * 3 + 0];
            sw[p * 12 + 8]  = W2[(e * 256 + h) * 3 + 1];
            sw[p * 12 + 9]  = W2[(e * 256 + h + 1) * 3 + 1];
            sw[p * 12 + 10] = W2[(e * 256 + h) * 3 + 2];
            sw[p * 12 + 11] = W2[(e * 256 + h + 1) * 3 + 2];
        }
        int rbase = e * CAP + tile * SPB;
        int rend  = e * CAP + g_cnt[e];
        __syncthreads();

        u64 xx0[SPT], xx1[SPT];
        #pragma unroll
        for (int t = 0; t < SPT; t++) {
            int slot = rbase + t * TPB + threadIdx.x;
            int idx  = (slot < rend) ? g_sidx[slot] : 0;
            float2 xy = __ldg(&s[idx]);
            xx0[t] = f2pack(xy.x, xy.x);
            xx1[t] = f2pack(xy.y, xy.y);
        }

        u64 acc0[SPT], acc1[SPT], acc2[SPT];
        #pragma unroll
        for (int t = 0; t < SPT; t++) { acc0[t] = 0ull; acc1[t] = 0ull; acc2[t] = 0ull; }

        const ulonglong2* swq = (const ulonglong2*)sw;
        #pragma unroll 8
        for (int p = 0; p < 128; p++) {
            ulonglong2 q0 = swq[p * 3 + 0];   // w0, w1
            ulonglong2 q1 = swq[p * 3 + 1];   // bb, v0
            ulonglong2 q2 = swq[p * 3 + 2];   // v1, v2
            #pragma unroll
            for (int t = 0; t < SPT; t++) {
                u64 h = f2fma(xx0[t], q0.x, f2fma(xx1[t], q0.y, q1.x));
                h = f2relu(h);
                acc0[t] = f2fma(h, q1.y, acc0[t]);
                acc1[t] = f2fma(h, q2.x, acc1[t]);
                acc2[t] = f2fma(h, q2.y, acc2[t]);
            }
        }

        float c0 = __ldg(&b2[e * 3 + 0]);
        float c1 = __ldg(&b2[e * 3 + 1]);
        float c2 = __ldg(&b2[e * 3 + 2]);
        #pragma unroll
        for (int t = 0; t < SPT; t++) {
            int slot = rbase + t * TPB + threadIdx.x;
            if (slot >= rend) continue;
            int idx = g_sidx[slot];           // L1 hit (read in prologue)
            float2 a0 = f2unpack(acc0[t]);
            float2 a1 = f2unpack(acc1[t]);
            float2 a2 = f2unpack(acc2[t]);
            float* o = out + (size_t)idx * 3;
            o[0] = a0.x + a0.y + c0;
            o[1] = a1.x + a1.y + c1;
            o[2] = a2.x + a2.y + c2;
        }
    }

    // per-replay state reset: last block to finish clears cursors/tickets
    if (threadIdx.x == 0) {
        __threadfence();
        if (atomicAdd(&g_fin, 1) == (int)gridDim.x - 1) {
            g_fin  = 0;
            g_done = 0;
            #pragma unroll
            for (int ee = 0; ee < NEXP; ee++) g_cur[ee * CSTRIDE] = 0;
        }
    }
}

// ---------------- launch ----------------
extern "C" void kernel_launch(void* const* d_in, const int* in_sizes, int n_in,
                              void* d_out, int out_size) {
    const float* samples = (const float*)d_in[0];
    const float* W1      = (const float*)d_in[1];
    const float* b1      = (const float*)d_in[2];
    const float* W2      = (const float*)d_in[3];
    const float* b2      = (const float*)d_in[4];
    float* out           = (float*)d_out;

    k_scatter<<<SBLK, 256>>>((const float2*)samples);
    k_mlp<<<MAXBLK, TPB>>>((const float2*)samples, W1, b1, W2, b2, out);
}

// round 16
// speedup vs baseline: 1.0421x; 1.0341x over previous
#include <cuda_runtime.h>
#include <cstdint>

// ---------------- problem constants ----------------
#define NS      524288
#define NEXP    16
#define HID     256
#define OUTD    3

// ---------------- tiling ----------------
#define TPB     128                 // threads per block (mlp)
#define SPT     8                   // samples per thread (mlp)
#define SPB     (TPB * SPT)         // 1024 samples per mlp tile
#define MAXBLK  ((NS / SPB) + NEXP) // 528 tiles upper bound
#define SBLK    512                 // scatter blocks
#define SSPT    4                   // 512 * 256 * 4 = 524288
#define CAP     NS                  // per-expert region capacity
#define CSTRIDE 32                  // cursor padding (128B apart)

typedef unsigned long long u64;

// ---------------- device scratch (static; zero-init is the "reset" state) ----------------
__device__ float2 g_sxy[NEXP * CAP];      // expert-partitioned sample coords
__device__ int    g_sidx[NEXP * CAP];     // expert-partitioned original indices
__device__ int    g_cur[NEXP * CSTRIDE];  // RELATIVE cursors (start at 0)
__device__ int    g_done;                 // scatter completion ticket
__device__ int    g_fin;                  // mlp completion ticket
__device__ int    g_cnt[NEXP];            // per-expert counts
__device__ int    g_bmap[MAXBLK];         // tile -> (expert<<16 | tile_in_expert), -1 idle

// ---------------- helpers ----------------
__device__ __forceinline__ int expert_of(float x0, float x1) {
    int i = (int)floorf(x0 * 4.0f);
    int j = (int)floorf(x1 * 4.0f);
    i = max(0, min(3, i));
    j = max(0, min(3, j));
    return j * 4 + i;
}
__device__ __forceinline__ u64 f2fma(u64 a, u64 b, u64 c) {
    u64 d;
    asm("fma.rn.f32x2 %0, %1, %2, %3;" : "=l"(d) : "l"(a), "l"(b), "l"(c));
    return d;
}
__device__ __forceinline__ u64 f2pack(float lo, float hi) {
    u64 d;
    asm("mov.b64 %0, {%1, %2};" : "=l"(d) : "f"(lo), "f"(hi));
    return d;
}
__device__ __forceinline__ float2 f2unpack(u64 v) {
    float2 r;
    asm("mov.b64 {%0, %1}, %2;" : "=f"(r.x), "=f"(r.y) : "l"(v));
    return r;
}
__device__ __forceinline__ u64 f2relu(u64 v) {
    float2 r = f2unpack(v);
    return f2pack(fmaxf(r.x, 0.0f), fmaxf(r.y, 0.0f));
}

// ---------------- K1: single-pass expert scatter (coords + index) + tile map ----------------
__global__ void __launch_bounds__(256) k_scatter(const float2* __restrict__ s) {
    __shared__ int sc[NEXP], sb[NEXP], sr[NEXP];
    int tid  = threadIdx.x;
    int lane = tid & 31;
    unsigned lt_mask = (1u << lane) - 1u;

    if (tid < NEXP) { sc[tid] = 0; sr[tid] = 0; }
    __syncthreads();

    int base = blockIdx.x * (256 * SSPT);
    float2 xy[SSPT]; int e[SSPT];

    // Phase 1: block histogram (warp-aggregated)
    #pragma unroll
    for (int t = 0; t < SSPT; t++) {
        xy[t] = s[base + t * 256 + tid];
        e[t]  = expert_of(xy[t].x, xy[t].y);
        unsigned m = __match_any_sync(0xffffffffu, e[t]);
        if ((__ffs(m) - 1) == lane) atomicAdd(&sc[e[t]], __popc(m));
    }
    __syncthreads();

    if (tid < NEXP) sb[tid] = atomicAdd(&g_cur[tid * CSTRIDE], sc[tid]);
    __syncthreads();

    // Phase 2: ranked scatter (warp-aggregated) — coords + index
    #pragma unroll
    for (int t = 0; t < SSPT; t++) {
        unsigned m = __match_any_sync(0xffffffffu, e[t]);
        int leader = __ffs(m) - 1;
        int rank   = __popc(m & lt_mask);
        int wbase  = 0;
        if (lane == leader) wbase = atomicAdd(&sr[e[t]], __popc(m));
        wbase = __shfl_sync(0xffffffffu, wbase, leader);
        int dst = e[t] * CAP + sb[e[t]] + wbase + rank;
        g_sxy[dst]  = xy[t];
        g_sidx[dst] = base + t * 256 + tid;
    }

    // Last block builds tile map
    __threadfence();
    __syncthreads();
    __shared__ int is_last;
    if (tid == 0) is_last = (atomicAdd(&g_done, 1) == gridDim.x - 1) ? 1 : 0;
    __syncthreads();
    if (!is_last) return;

    __shared__ int cnt[NEXP], toff[NEXP + 1];
    if (tid < NEXP) cnt[tid] = g_cur[tid * CSTRIDE];
    __syncthreads();
    if (tid == 0) {
        int o = 0;
        for (int ee = 0; ee < NEXP; ee++) {
            toff[ee] = o;
            o += (cnt[ee] + SPB - 1) / SPB;
        }
        toff[NEXP] = o;
    }
    __syncthreads();
    for (int b = tid; b < MAXBLK; b += 256) g_bmap[b] = -1;
    if (tid < NEXP) g_cnt[tid] = cnt[tid];
    __syncthreads();
    if (tid < NEXP) {
        int ntile = toff[tid + 1] - toff[tid];
        for (int t = 0; t < ntile; t++)
            g_bmap[toff[tid] + t] = (tid << 16) | t;
    }
}

// ---------------- K2: expert-uniform fused MLP (pipelined weight fetch) ----------------
__global__ void __launch_bounds__(TPB, 4) k_mlp(const float2* __restrict__ s,
                                                const float* __restrict__ W1,
                                                const float* __restrict__ b1,
                                                const float* __restrict__ W2,
                                                const float* __restrict__ b2,
                                                float* __restrict__ out) {
    int v = g_bmap[blockIdx.x];
    // packed weights: per hidden pair p (12 floats = 3 x ulonglong2):
    // [w0lo w0hi | w1lo w1hi | bblo bbhi | v0lo v0hi | v1lo v1hi | v2lo v2hi]
    // +1 padding group so the software-pipelined prefetch can over-read at p=127
    __shared__ float sw[129 * 12];

    if (v >= 0) {
        int e    = v >> 16;
        int tile = v & 0xffff;

        {
            int p = threadIdx.x;   // TPB == 128 == number of hidden pairs
            int h = 2 * p;
            sw[p * 12 + 0]  = W1[e * 512 + h];
            sw[p * 12 + 1]  = W1[e * 512 + h + 1];
            sw[p * 12 + 2]  = W1[e * 512 + 256 + h];
            sw[p * 12 + 3]  = W1[e * 512 + 256 + h + 1];
            sw[p * 12 + 4]  = b1[e * 256 + h];
            sw[p * 12 + 5]  = b1[e * 256 + h + 1];
            sw[p * 12 + 6]  = W2[(e * 256 + h) * 3 + 0];
            sw[p * 12 + 7]  = W2[(e * 256 + h + 1) * 3 + 0];
            sw[p * 12 + 8]  = W2[(e * 256 + h) * 3 + 1];
            sw[p * 12 + 9]  = W2[(e * 256 + h + 1) * 3 + 1];
            sw[p * 12 + 10] = W2[(e * 256 + h) * 3 + 2];
            sw[p * 12 + 11] = W2[(e * 256 + h + 1) * 3 + 2];
            if (p < 12) sw[128 * 12 + p] = 0.0f;   // padding group
        }
        int rbase = e * CAP + tile * SPB;
        int rend  = e * CAP + g_cnt[e];
        __syncthreads();

        // coalesced coord load (no dependent gather)
        u64 xx0[SPT], xx1[SPT];
        #pragma unroll
        for (int t = 0; t < SPT; t++) {
            int slot = rbase + t * TPB + threadIdx.x;
            float2 xy = g_sxy[(slot < rend) ? slot : rbase];
            xx0[t] = f2pack(xy.x, xy.x);
            xx1[t] = f2pack(xy.y, xy.y);
        }

        u64 acc0[SPT], acc1[SPT], acc2[SPT];
        #pragma unroll
        for (int t = 0; t < SPT; t++) { acc0[t] = 0ull; acc1[t] = 0ull; acc2[t] = 0ull; }

        const ulonglong2* swq = (const ulonglong2*)sw;

        // software-pipelined: prefetch p+1's weights before computing p
        ulonglong2 q0 = swq[0];   // w0, w1
        ulonglong2 q1 = swq[1];   // bb, v0
        ulonglong2 q2 = swq[2];   // v1, v2
        #pragma unroll 4
        for (int p = 0; p < 128; p++) {
            ulonglong2 n0 = swq[(p + 1) * 3 + 0];
            ulonglong2 n1 = swq[(p + 1) * 3 + 1];
            ulonglong2 n2 = swq[(p + 1) * 3 + 2];
            #pragma unroll
            for (int t = 0; t < SPT; t++) {
                u64 h = f2fma(xx0[t], q0.x, f2fma(xx1[t], q0.y, q1.x));
                h = f2relu(h);
                acc0[t] = f2fma(h, q1.y, acc0[t]);
                acc1[t] = f2fma(h, q2.x, acc1[t]);
                acc2[t] = f2fma(h, q2.y, acc2[t]);
            }
            q0 = n0; q1 = n1; q2 = n2;
        }

        float c0 = __ldg(&b2[e * 3 + 0]);
        float c1 = __ldg(&b2[e * 3 + 1]);
        float c2 = __ldg(&b2[e * 3 + 2]);
        #pragma unroll
        for (int t = 0; t < SPT; t++) {
            int slot = rbase + t * TPB + threadIdx.x;
            if (slot >= rend) continue;
            int idx = g_sidx[slot];           // coalesced
            float2 a0 = f2unpack(acc0[t]);
            float2 a1 = f2unpack(acc1[t]);
            float2 a2 = f2unpack(acc2[t]);
            float* o = out + (size_t)idx * 3;
            o[0] = a0.x + a0.y + c0;
            o[1] = a1.x + a1.y + c1;
            o[2] = a2.x + a2.y + c2;
        }
    }

    // per-replay state reset: last block to finish clears cursors/tickets
    if (threadIdx.x == 0) {
        __threadfence();
        if (atomicAdd(&g_fin, 1) == (int)gridDim.x - 1) {
            g_fin  = 0;
            g_done = 0;
            #pragma unroll
            for (int ee = 0; ee < NEXP; ee++) g_cur[ee * CSTRIDE] = 0;
        }
    }
}

// ---------------- launch ----------------
extern "C" void kernel_launch(void* const* d_in, const int* in_sizes, int n_in,
                              void* d_out, int out_size) {
    const float* samples = (const float*)d_in[0];
    const float* W1      = (const float*)d_in[1];
    const float* b1      = (const float*)d_in[2];
    const float* W2      = (const float*)d_in[3];
    const float* b2      = (const float*)d_in[4];
    float* out           = (float*)d_out;

    k_scatter<<<SBLK, 256>>>((const float2*)samples);
    k_mlp<<<MAXBLK, TPB>>>((const float2*)samples, W1, b1, W2, b2, out);
}